// round 15
// baseline (speedup 1.0000x reference)
#include <cuda_runtime.h>
#include <cuda_fp16.h>

// PowerFlowUnconstrainedSuperNodeGNN — GB300, round 14
//
// agg[r] = sum_e m_e * (node_in[s_e] @ Wm)  + EF_agg[r] @ Wm_ef + cntf[r]*b
// Projected node features P stored FP16 (fp32 accumulate) => 64B/edge gather.
// SpMM core = round-8 SHFL-broadcast form (best measured). Supernode update
// fused into k_node (per-layer pool slots). 4-way ILP in hist/scatter.

#define NN 100000
#define EE 3200000
#define HD 32
#define NL 3
#define FULL 0xffffffffu

__device__ int    d_cnt[NN];
__device__ int    d_rs[NN + 1];
__device__ int    d_fill[NN];
__device__ int2   d_sm[EE];        // (src, mask bits) in CSR order
__device__ int    d_eid[EE];       // original edge id in CSR order
__device__ __half d_Ph[(size_t)NN * HD];  // projected node features (fp16)
__device__ float  d_h[(size_t)NN * HD];
__device__ float2 d_V[NN];
__device__ float4 d_EF[NN];
__device__ float  d_cntf[NN];
__device__ float  d_pool[NL * HD];

// ------------------------------------------- histogram, 4 chains per thread
__global__ void k_hist(const int* __restrict__ rcv, int e) {
    int i = blockIdx.x * 1024 + threadIdx.x;
#pragma unroll
    for (int s = 0; s < 4; s++) {
        int idx = i + s * 256;
        if (idx < e) atomicAdd(&d_cnt[rcv[idx]], 1);
    }
}

// --------------------- exclusive scan (1 block); also seeds d_fill = rs
__global__ void k_scan(int n) {
    __shared__ int part[1024];
    int t = threadIdx.x;
    int chunk = (n + 1023) >> 10;
    int lo = t * chunk;
    int hi = min(lo + chunk, n);
    int s = 0;
    for (int i = lo; i < hi; i++) s += d_cnt[i];
    part[t] = s;
    __syncthreads();
    for (int off = 1; off < 1024; off <<= 1) {
        int v = (t >= off) ? part[t - off] : 0;
        __syncthreads();
        part[t] += v;
        __syncthreads();
    }
    int run = (t == 0) ? 0 : part[t - 1];
    for (int i = lo; i < hi; i++) {
        d_rs[i] = run;
        d_fill[i] = run;
        run += d_cnt[i];
    }
    if (t == 1023) d_rs[n] = part[1023];
}

// ----------------- scatter edges into CSR slots, 4 independent atomic chains
__global__ void k_scatter(const int* __restrict__ snd, const int* __restrict__ rcv,
                          const float* __restrict__ mk, int e) {
    int i = blockIdx.x * 1024 + threadIdx.x;
#pragma unroll
    for (int s = 0; s < 4; s++) {
        int idx = i + s * 256;
        if (idx < e) {
            int p = atomicAdd(&d_fill[rcv[idx]], 1);
            d_sm[p] = make_int2(snd[idx], __float_as_int(mk[idx]));
            d_eid[p] = idx;
        }
    }
}

// ---------------- layer-invariant EF aggregate + masked degree, atomic-free
__global__ void k_ef(const float* __restrict__ ef, int n) {
    int w = (blockIdx.x * blockDim.x + threadIdx.x) >> 5;
    int c = threadIdx.x & 31;
    if (w >= n) return;
    int s0 = d_rs[w], s1 = d_rs[w + 1];
    float ax = 0.f, ay = 0.f, az = 0.f, aw = 0.f, cnt = 0.f;
    for (int e = s0 + c; e < s1; e += 32) {
        float m = __int_as_float(d_sm[e].y);
        int id = __ldg(d_eid + e);
        const float4 f = *reinterpret_cast<const float4*>(ef + (size_t)id * 4);
        ax = fmaf(m, f.x, ax); ay = fmaf(m, f.y, ay);
        az = fmaf(m, f.z, az); aw = fmaf(m, f.w, aw);
        cnt += m;
    }
#pragma unroll
    for (int o = 16; o; o >>= 1) {
        ax += __shfl_xor_sync(FULL, ax, o);
        ay += __shfl_xor_sync(FULL, ay, o);
        az += __shfl_xor_sync(FULL, az, o);
        aw += __shfl_xor_sync(FULL, aw, o);
        cnt += __shfl_xor_sync(FULL, cnt, o);
    }
    if (c == 0) { d_EF[w] = make_float4(ax, ay, az, aw); d_cntf[w] = cnt; }
}

// --------------- init: V=(1,0), h0 = PQ@Win + bin, P0 = [V0,h0]@Wm[0][0:34]
__global__ void k_init(const float* __restrict__ PQ, const float* __restrict__ Win,
                       const float* __restrict__ bin, const float* __restrict__ Wm0,
                       int n) {
    int w = (blockIdx.x * blockDim.x + threadIdx.x) >> 5;
    int c = threadIdx.x & 31;
    if (w >= n) return;
    float p = __ldg(PQ + (size_t)w * 2);
    float q = __ldg(PQ + (size_t)w * 2 + 1);
    float hv = fmaf(p, __ldg(Win + c), fmaf(q, __ldg(Win + HD + c), __ldg(bin + c)));
    float pacc = __ldg(Wm0 + c);                 // V0 = (1, 0): only row 0 counts
#pragma unroll
    for (int k = 0; k < HD; k++)
        pacc = fmaf(__shfl_sync(FULL, hv, k), __ldg(Wm0 + (2 + k) * HD + c), pacc);
    d_Ph[(size_t)w * HD + c] = __float2half_rn(pacc);
    if (c == 0) d_V[w] = make_float2(1.f, 0.f);
}

// ---- SpMM + epilogue: h[r]=relu( sum m*P[s] + EF@Wm_ef + cntf*b ); pool[l].
// Round-8 SHFL-broadcast core, fp16 gathers (fp32 accumulate).
__global__ void __launch_bounds__(256) k_spmm(const float* __restrict__ Wt,
                                              const float* __restrict__ bm,
                                              float* __restrict__ pool, int n) {
    __shared__ float bp[HD];
    int tid = threadIdx.x;
    if (tid < HD) bp[tid] = 0.f;
    __syncthreads();
    int w = (blockIdx.x * blockDim.x + tid) >> 5;
    int c = tid & 31;
    if (w < n) {
        int s0 = d_rs[w], s1 = d_rs[w + 1];
        float acc = 0.f;
        const __half* Pc = d_Ph + c;
        int base = s0;
        for (; base + 32 <= s1; base += 32) {
            int2 sm = d_sm[base + c];
#pragma unroll
            for (int j = 0; j < 32; j++) {
                int   src = __shfl_sync(FULL, sm.x, j);
                float m   = __int_as_float(__shfl_sync(FULL, sm.y, j));
                acc = fmaf(m, __half2float(__ldg(Pc + ((size_t)src << 5))), acc);
            }
        }
        if (base < s1) {
            int idx = base + c;
            int2 sm = (idx < s1) ? d_sm[idx] : make_int2(0, 0);
            int lim = s1 - base;
#pragma unroll 4
            for (int j = 0; j < lim; j++) {
                int   src = __shfl_sync(FULL, sm.x, j);
                float m   = __int_as_float(__shfl_sync(FULL, sm.y, j));
                acc = fmaf(m, __half2float(__ldg(Pc + ((size_t)src << 5))), acc);
            }
        }
        const float4 f = d_EF[w];
        acc = fmaf(f.x, __ldg(Wt + c),          acc);
        acc = fmaf(f.y, __ldg(Wt + HD + c),     acc);
        acc = fmaf(f.z, __ldg(Wt + 2 * HD + c), acc);
        acc = fmaf(f.w, __ldg(Wt + 3 * HD + c), acc);
        acc = fmaf(__ldg(d_cntf + w), __ldg(bm + c), acc);
        acc = fmaxf(acc, 0.f);
        d_h[(size_t)w * HD + c] = acc;
        atomicAdd(&bp[c], acc);
    }
    __syncthreads();
    if (tid < HD) atomicAdd(&pool[tid], bp[tid]);
}

// --- node update (supernode fused): recompute g-chain from pools, then
//     h'=relu([h,g]@Wn+bn); V+=h'@Wo+bo; P_next=[V',h']@Wm_next (fp16)
__global__ void k_node(const float* __restrict__ Wn, const float* __restrict__ bn,
                       const float* __restrict__ Wo, const float* __restrict__ bo,
                       const float* __restrict__ Wm_next,
                       const float* __restrict__ Wg, const float* __restrict__ bg,
                       float* __restrict__ out, int n, int l, float inv_n) {
    __shared__ float gg[HD];
    __shared__ float gbuf[2 * HD];
    if (threadIdx.x < 32) {
        int t = threadIdx.x;
        float g = 0.f;
        for (int j = 0; j <= l; j++) {
            gbuf[t] = g;
            gbuf[HD + t] = d_pool[j * HD + t] * inv_n;
            __syncwarp();
            const float* Wgj = Wg + (size_t)j * 2 * HD * HD;
            float a = __ldg(bg + j * HD + t);
#pragma unroll
            for (int k = 0; k < 2 * HD; k++)
                a = fmaf(gbuf[k], __ldg(Wgj + k * HD + t), a);
            g = fmaxf(a, 0.f);
            __syncwarp();
        }
        gg[t] = g;
    }
    __syncthreads();
    int w = (blockIdx.x * blockDim.x + threadIdx.x) >> 5;
    int c = threadIdx.x & 31;
    if (w >= n) return;
    const float* hrow = d_h + (size_t)w * HD;
    float a = __ldg(bn + c);
#pragma unroll
    for (int k = 0; k < HD; k++) a = fmaf(__ldg(hrow + k), __ldg(Wn + k * HD + c), a);
#pragma unroll
    for (int k = 0; k < HD; k++) a = fmaf(gg[k], __ldg(Wn + (HD + k) * HD + c), a);
    a = fmaxf(a, 0.f);
    float p0 = a * __ldg(Wo + c * 2);
    float p1 = a * __ldg(Wo + c * 2 + 1);
#pragma unroll
    for (int o = 16; o; o >>= 1) {
        p0 += __shfl_xor_sync(FULL, p0, o);
        p1 += __shfl_xor_sync(FULL, p1, o);
    }
    float2 V = d_V[w];
    float v0 = V.x + p0 + __ldg(bo);
    float v1 = V.y + p1 + __ldg(bo + 1);
    if (c == 0) d_V[w] = make_float2(v0, v1);
    if (out) {
        if (c == 0) reinterpret_cast<float2*>(out)[w] = make_float2(v0, v1);
    } else {
        float pacc = fmaf(v0, __ldg(Wm_next + c),
                     fmaf(v1, __ldg(Wm_next + HD + c), 0.f));
#pragma unroll
        for (int k = 0; k < HD; k++)
            pacc = fmaf(__shfl_sync(FULL, a, k), __ldg(Wm_next + (2 + k) * HD + c), pacc);
        d_Ph[(size_t)w * HD + c] = __float2half_rn(pacc);
    }
}

extern "C" void kernel_launch(void* const* d_in, const int* in_sizes, int n_in,
                              void* d_out, int out_size) {
    const float* PQ  = (const float*)d_in[0];
    const int*   snd = (const int*)  d_in[1];
    const int*   rcv = (const int*)  d_in[2];
    const float* ef  = (const float*)d_in[3];
    const float* mk  = (const float*)d_in[4];
    const float* Win = (const float*)d_in[5];
    const float* bin = (const float*)d_in[6];
    const float* Wm  = (const float*)d_in[7];   // (L,38,32)
    const float* bm  = (const float*)d_in[8];   // (L,32)
    const float* Wg  = (const float*)d_in[9];   // (L,64,32)
    const float* bg  = (const float*)d_in[10];
    const float* Wn  = (const float*)d_in[11];  // (L,64,32)
    const float* bn  = (const float*)d_in[12];
    const float* Wo  = (const float*)d_in[13];  // (L,32,2)
    const float* bo  = (const float*)d_in[14];  // (L,2)

    int n = in_sizes[0] / 2;
    int e = in_sizes[1];
    if (n > NN) n = NN;
    if (e > EE) e = EE;
    float* out = (float*)d_out;

    void* p_cnt = nullptr;
    void* p_pool = nullptr;
    cudaGetSymbolAddress(&p_cnt, d_cnt);
    cudaGetSymbolAddress(&p_pool, d_pool);

    int nb_e4 = (e + 1023) / 1024;
    int nb_w = (int)(((long long)n * 32 + 255) / 256);

    cudaMemsetAsync(p_cnt, 0, (size_t)n * sizeof(int));
    cudaMemsetAsync(p_pool, 0, (size_t)NL * HD * sizeof(float));
    k_hist<<<nb_e4, 256>>>(rcv, e);
    k_scan<<<1, 1024>>>(n);
    k_scatter<<<nb_e4, 256>>>(snd, rcv, mk, e);
    k_ef<<<nb_w, 256>>>(ef, n);
    k_init<<<nb_w, 256>>>(PQ, Win, bin, Wm, n);

    float* poolp = nullptr;
    cudaGetSymbolAddress((void**)&poolp, d_pool);

    for (int l = 0; l < NL; l++) {
        k_spmm<<<nb_w, 256>>>(Wm + (size_t)l * 38 * HD + 34 * HD,
                              bm + (size_t)l * HD,
                              poolp + (size_t)l * HD, n);
        k_node<<<nb_w, 256>>>(Wn + (size_t)l * 64 * HD, bn + (size_t)l * HD,
                              Wo + (size_t)l * HD * 2, bo + (size_t)l * 2,
                              (l < NL - 1) ? (Wm + (size_t)(l + 1) * 38 * HD) : nullptr,
                              Wg, bg,
                              (l == NL - 1) ? out : nullptr, n, l, 1.0f / (float)n);
    }
}